// round 12
// baseline (speedup 1.0000x reference)
#include <cuda_runtime.h>
#include <cstdint>

#define RES   512
#define NPTS  1024            // 8 curves * 128 steps
// exponent in cell units: (xk - i/512)^2*5000 == (xi - i)^2 * (5000/2^18)
#define INVC_CELL 0.019073486328125f   // 5000 / 262144, exact in fp32
// Dropped terms <= exp(-5000*(36/512)^2) = 1.8e-11 each (validated).
#define BAND  36.0f

#define STRIPS 32             // i-strips of width TI
#define TI  16                // tile i
#define TJ  16                // tile j

// Per-strip compacted point lists (cell coords) + j-tile occupancy masks.
__device__ float2   g_spt[STRIPS][NPTS];
__device__ int      g_sn[STRIPS];
__device__ unsigned g_mask[STRIPS];

// ---------------------------------------------------------------------------
// Kernel A: Bezier evaluation + per-i-strip compaction + j-tile bitmask.
// (unchanged from the passing Round-11 kernel)
// ---------------------------------------------------------------------------
__global__ __launch_bounds__(128) void k_prep(const float* __restrict__ curves) {
    __shared__ int wsum[4], woff[4];
    __shared__ unsigned smask;
    const int tid = threadIdx.x, lane = tid & 31, wid = tid >> 5;
    const int strip = blockIdx.x;
    const float ilo = (float)(strip * TI) - BAND;
    const float ihi = (float)(strip * TI + TI - 1) + BAND;
    if (tid == 0) smask = 0u;
    __syncthreads();

    float xi[8], yi[8];
    bool ok[8];
    int cnt = 0;
    unsigned mybits = 0u;
    const int kb = tid * 8;                  // 8 consecutive k, same curve
    const int c  = kb >> 7;
    const float* P = curves + c * 8;
    float p0x = __ldg(P+0), p0y = __ldg(P+1), p1x = __ldg(P+2), p1y = __ldg(P+3);
    float p2x = __ldg(P+4), p2y = __ldg(P+5), p3x = __ldg(P+6), p3y = __ldg(P+7);
    #pragma unroll
    for (int u = 0; u < 8; u++) {
        float t = (float)((kb + u) & 127) * (1.0f / 127.0f);
        float a01 = p0x + (p1x - p0x) * t;
        float a12 = p1x + (p2x - p1x) * t;
        float a23 = p2x + (p3x - p2x) * t;
        float qa  = a01 + t * (a12 - a01);
        float qb  = a12 + t * (a23 - a12);
        xi[u] = (qa + t * (qb - qa)) * (float)RES;
        a01 = p0y + (p1y - p0y) * t;
        a12 = p1y + (p2y - p1y) * t;
        a23 = p2y + (p3y - p2y) * t;
        qa  = a01 + t * (a12 - a01);
        qb  = a12 + t * (a23 - a12);
        yi[u] = (qa + t * (qb - qa)) * (float)RES;
        ok[u] = (xi[u] >= ilo) & (xi[u] <= ihi);
        cnt += ok[u] ? 1 : 0;
        if (ok[u]) {
            // jtile jt touched iff  jt*16 - BAND <= y <= jt*16 + 15 + BAND
            int jt0 = (int)ceilf((yi[u] - 15.0f - BAND) * (1.0f / 16.0f));
            int jt1 = (int)floorf((yi[u] + BAND) * (1.0f / 16.0f));
            jt0 = jt0 < 0 ? 0 : jt0;
            jt1 = jt1 > 31 ? 31 : jt1;
            if (jt1 >= jt0)
                mybits |= (0xFFFFFFFFu >> (31 - jt1)) & (0xFFFFFFFFu << jt0);
        }
    }
    if (mybits) atomicOr(&smask, mybits);

    int inc = cnt;                           // warp inclusive scan
    #pragma unroll
    for (int d = 1; d < 32; d <<= 1) {
        int n = __shfl_up_sync(0xffffffffu, inc, d);
        if (lane >= d) inc += n;
    }
    if (lane == 31) wsum[wid] = inc;
    __syncthreads();
    if (tid == 0) {
        int s = 0;
        #pragma unroll
        for (int w = 0; w < 4; w++) { woff[w] = s; s += wsum[w]; }
        g_sn[strip] = s;
        g_mask[strip] = smask;
    }
    __syncthreads();
    int off = woff[wid] + inc - cnt;
    #pragma unroll
    for (int u = 0; u < 8; u++)
        if (ok[u]) g_spt[strip][off++] = make_float2(xi[u], yi[u]);
}

// ---------------------------------------------------------------------------
// Kernel B: one 16x16 tile per block (grid 32x32), 128 threads = 4 warps.
//  0. bitmask early-out (empty tiles: zero-write, exit)
//  1. load strip point list into smem
//  2. each warp scans an interleaved share of the list (ballot), and for each
//     accepted point does warp-split exp (lanes 0-15: ex, 16-31: ey) + shfl
//     distribution + 8 FMA. No block barriers in the main loop.
//  3. fixed-order 4-warp partial reduction via smem, write tile.
// ---------------------------------------------------------------------------
__global__ __launch_bounds__(128) void k_tile(float* __restrict__ out) {
    __shared__ float2 spt[NPTS];             // 8 KB
    __shared__ float  sacc[4][32][8];        // 4 KB

    const int tid = threadIdx.x, lane = tid & 31, w = tid >> 5;
    const int strip = blockIdx.x;
    const int i0 = strip * TI;
    const int j0 = blockIdx.y * TJ;

    // ---- 0. early-out on empty tiles --------------------------------------
    if (!((g_mask[strip] >> blockIdx.y) & 1u)) {
        if (tid < 64)
            *(float4*)&out[(j0 + (tid >> 2)) * RES + i0 + (tid & 3) * 4] =
                make_float4(0.f, 0.f, 0.f, 0.f);
        return;
    }
    const int n = g_sn[strip];

    // ---- 1. load point list (2 points per float4) -------------------------
    for (int idx = tid; idx < ((n + 1) >> 1); idx += 128)
        *(float4*)&spt[idx * 2] = *(const float4*)&g_spt[strip][idx * 2];
    __syncthreads();

    // ---- 2. warp-synchronous per-point accumulation -----------------------
    const float jlo = (float)j0 - BAND, jhi = (float)(j0 + TJ - 1) + BAND;
    const int li = lane & 3;                 // i-group of 4 (i = i0+li*4+m)
    const int lj = lane >> 2;                // j-pair       (j = j0+lj*2+jj)
    const bool is_ey = lane >= 16;
    const float bcoord = is_ey ? (float)(j0 + (lane - 16))
                               : (float)(i0 + lane);
    float acc[8];
    #pragma unroll
    for (int s = 0; s < 8; s++) acc[s] = 0.f;

    for (int base = w * 32; base < n; base += 128) {
        int k = base + lane;
        bool ok = (k < n);
        float yv = ok ? spt[k].y : -1.0e9f;
        ok = ok & (yv >= jlo) & (yv <= jhi);
        unsigned m = __ballot_sync(0xffffffffu, ok);
        while (m) {
            int b = __ffs(m) - 1;
            m &= m - 1;
            float2 p = spt[base + b];        // LDS broadcast
            float ctr = is_ey ? p.y : p.x;
            float d = ctr - bcoord;
            float e = __expf(-d * d * INVC_CELL);
            float ex0 = __shfl_sync(0xffffffffu, e, li * 4 + 0);
            float ex1 = __shfl_sync(0xffffffffu, e, li * 4 + 1);
            float ex2 = __shfl_sync(0xffffffffu, e, li * 4 + 2);
            float ex3 = __shfl_sync(0xffffffffu, e, li * 4 + 3);
            float ey0 = __shfl_sync(0xffffffffu, e, 16 + lj * 2 + 0);
            float ey1 = __shfl_sync(0xffffffffu, e, 16 + lj * 2 + 1);
            acc[0] += ex0 * ey0;  acc[1] += ex1 * ey0;
            acc[2] += ex2 * ey0;  acc[3] += ex3 * ey0;
            acc[4] += ex0 * ey1;  acc[5] += ex1 * ey1;
            acc[6] += ex2 * ey1;  acc[7] += ex3 * ey1;
        }
    }

    // ---- 3. fixed-order cross-warp reduction + write ----------------------
    #pragma unroll
    for (int s = 0; s < 8; s++) sacc[w][lane][s] = acc[s];
    __syncthreads();
    {
        int l  = tid & 31;
        int s0 = (tid >> 5) * 2;             // each thread: 2 slots of lane l
        int lli = l & 3, llj = l >> 2;
        #pragma unroll
        for (int s = s0; s < s0 + 2; s++) {
            float v = sacc[0][l][s] + sacc[1][l][s]
                    + sacc[2][l][s] + sacc[3][l][s];
            int mm = s & 3, jj = s >> 2;
            out[(j0 + llj * 2 + jj) * RES + i0 + lli * 4 + mm] = v;
        }
    }
}

// ---------------------------------------------------------------------------
extern "C" void kernel_launch(void* const* d_in, const int* in_sizes, int n_in,
                              void* d_out, int out_size) {
    const float* curves = (const float*)d_in[0];
    float* out = (float*)d_out;
    k_prep<<<STRIPS, 128>>>(curves);
    dim3 grid(STRIPS, RES / TJ);
    k_tile<<<grid, 128>>>(out);
}

// round 13
// speedup vs baseline: 1.3535x; 1.3535x over previous
#include <cuda_runtime.h>
#include <cstdint>

#define RES   512
#define NPTS  1024            // 8 curves * 128 steps
// exponent in cell units: (xk - i/512)^2*5000 == (xi - i)^2 * (5000/2^18)
#define INVC_CELL 0.019073486328125f   // 5000 / 262144, exact in fp32
// Dropped terms <= exp(-5000*(30/512)^2) = 3.5e-8 each, worst-case ~4e-5
// absolute vs 1e-3 global-norm gate (BAND=36 was bit-identical to dense).
#define BAND  30.0f

#define STRIPS 32             // i-strips of width TI
#define TI  16                // tile i
#define TJ  16                // tile j
#define BKC 32                // k per staging chunk (per group)

// packed f32x2 FMA: d = a*b + d
#define FMA_F32X2(d, a, b) \
    asm("fma.rn.f32x2 %0, %1, %2, %0;" : "+l"(d) : "l"(a), "l"(b))
#define PACK_DUP(out, v) \
    asm("mov.b64 %0, {%1, %1};" : "=l"(out) : "r"(v))
#define UNPACK_F32X2(lo, hi, in) \
    asm("mov.b64 {%0, %1}, %2;" : "=r"(lo), "=r"(hi) : "l"(in))

// Per-strip compacted point lists (cell coords) + j-tile occupancy masks.
__device__ float2   g_spt[STRIPS][NPTS];
__device__ int      g_sn[STRIPS];
__device__ unsigned g_mask[STRIPS];

// ---------------------------------------------------------------------------
// Kernel A: Bezier evaluation + per-i-strip compaction + j-tile bitmask.
// (structure unchanged from the passing Round-11 kernel)
// ---------------------------------------------------------------------------
__global__ __launch_bounds__(128) void k_prep(const float* __restrict__ curves) {
    __shared__ int wsum[4], woff[4];
    __shared__ unsigned smask;
    const int tid = threadIdx.x, lane = tid & 31, wid = tid >> 5;
    const int strip = blockIdx.x;
    const float ilo = (float)(strip * TI) - BAND;
    const float ihi = (float)(strip * TI + TI - 1) + BAND;
    if (tid == 0) smask = 0u;
    __syncthreads();

    float xi[8], yi[8];
    bool ok[8];
    int cnt = 0;
    unsigned mybits = 0u;
    const int kb = tid * 8;                  // 8 consecutive k, same curve
    const int c  = kb >> 7;
    const float* P = curves + c * 8;
    float p0x = __ldg(P+0), p0y = __ldg(P+1), p1x = __ldg(P+2), p1y = __ldg(P+3);
    float p2x = __ldg(P+4), p2y = __ldg(P+5), p3x = __ldg(P+6), p3y = __ldg(P+7);
    #pragma unroll
    for (int u = 0; u < 8; u++) {
        float t = (float)((kb + u) & 127) * (1.0f / 127.0f);
        float a01 = p0x + (p1x - p0x) * t;
        float a12 = p1x + (p2x - p1x) * t;
        float a23 = p2x + (p3x - p2x) * t;
        float qa  = a01 + t * (a12 - a01);
        float qb  = a12 + t * (a23 - a12);
        xi[u] = (qa + t * (qb - qa)) * (float)RES;
        a01 = p0y + (p1y - p0y) * t;
        a12 = p1y + (p2y - p1y) * t;
        a23 = p2y + (p3y - p2y) * t;
        qa  = a01 + t * (a12 - a01);
        qb  = a12 + t * (a23 - a12);
        yi[u] = (qa + t * (qb - qa)) * (float)RES;
        ok[u] = (xi[u] >= ilo) & (xi[u] <= ihi);
        cnt += ok[u] ? 1 : 0;
        if (ok[u]) {
            // jtile jt touched iff  jt*16 - BAND <= y <= jt*16 + 15 + BAND
            int jt0 = (int)ceilf((yi[u] - 15.0f - BAND) * (1.0f / 16.0f));
            int jt1 = (int)floorf((yi[u] + BAND) * (1.0f / 16.0f));
            jt0 = jt0 < 0 ? 0 : jt0;
            jt1 = jt1 > 31 ? 31 : jt1;
            if (jt1 >= jt0)
                mybits |= (0xFFFFFFFFu >> (31 - jt1)) & (0xFFFFFFFFu << jt0);
        }
    }
    if (mybits) atomicOr(&smask, mybits);

    int inc = cnt;                           // warp inclusive scan
    #pragma unroll
    for (int d = 1; d < 32; d <<= 1) {
        int n = __shfl_up_sync(0xffffffffu, inc, d);
        if (lane >= d) inc += n;
    }
    if (lane == 31) wsum[wid] = inc;
    __syncthreads();
    if (tid == 0) {
        int s = 0;
        #pragma unroll
        for (int w = 0; w < 4; w++) { woff[w] = s; s += wsum[w]; }
        g_sn[strip] = s;
        g_mask[strip] = smask;
    }
    __syncthreads();
    int off = woff[wid] + inc - cnt;
    #pragma unroll
    for (int u = 0; u < 8; u++)
        if (ok[u]) g_spt[strip][off++] = make_float2(xi[u], yi[u]);
}

// ---------------------------------------------------------------------------
// Kernel B: one 16x16 tile per block (grid 32x32), 128 threads = 2 groups
// of 64 doing intra-block split-K over chunks (named barriers per group).
//  0. bitmask early-out
//  1. load strip point list
//  2. one-pass y-filter + compaction (4 warps)
//  3. per group: alternating chunks of 32, exp-recompute staging + FMA2
//  4. fixed-order group0+group1 combine, write tile
// ---------------------------------------------------------------------------
__global__ __launch_bounds__(128) void k_tile(float* __restrict__ out) {
    __shared__ float2 spt[NPTS];             // 8 KB
    __shared__ unsigned short list[NPTS];    // 2 KB
    __shared__ float sex[2][BKC][TI];        // 4 KB
    __shared__ float sey[2][BKC][TJ];        // 4 KB
    __shared__ ulonglong2 gred[64];          // 1 KB (group-1 partials)
    __shared__ int wsum[4];

    const int tid = threadIdx.x, lane = tid & 31, wid = tid >> 5;
    const int strip = blockIdx.x;
    const int i0 = strip * TI;
    const int j0 = blockIdx.y * TJ;

    // ---- 0. early-out on empty tiles --------------------------------------
    if (!((g_mask[strip] >> blockIdx.y) & 1u)) {
        if (tid < 64)
            *(float4*)&out[(j0 + (tid >> 2)) * RES + i0 + (tid & 3) * 4] =
                make_float4(0.f, 0.f, 0.f, 0.f);
        return;
    }
    const int n = g_sn[strip];

    // ---- 1. load point list (2 points per float4) -------------------------
    for (int idx = tid; idx < ((n + 1) >> 1); idx += 128)
        *(float4*)&spt[idx * 2] = *(const float4*)&g_spt[strip][idx * 2];
    __syncthreads();

    // ---- 2. one-pass y-filter + order-preserving compaction (4 warps) -----
    const float jlo = (float)j0 - BAND, jhi = (float)(j0 + TJ - 1) + BAND;
    const int m  = (n + 127) >> 7;           // contiguous segment per thread
    const int b0 = tid * m;
    const int b1 = (b0 + m < n) ? b0 + m : n;
    int cnt = 0;
    for (int k = b0; k < b1; k++)
        cnt += (spt[k].y >= jlo) & (spt[k].y <= jhi);
    int inc = cnt;
    #pragma unroll
    for (int d = 1; d < 32; d <<= 1) {
        int v = __shfl_up_sync(0xffffffffu, inc, d);
        if (lane >= d) inc += v;
    }
    if (lane == 31) wsum[wid] = inc;
    __syncthreads();
    int pre = 0;
    #pragma unroll
    for (int w = 0; w < 4; w++) if (w < wid) pre += wsum[w];
    const int nk = wsum[0] + wsum[1] + wsum[2] + wsum[3];
    int off = pre + (inc - cnt);
    for (int k = b0; k < b1; k++)
        if ((spt[k].y >= jlo) & (spt[k].y <= jhi))
            list[off++] = (unsigned short)k;
    __syncthreads();

    // ---- 3. per-group chunked recompute + FMA2 accumulate -----------------
    const int g    = tid >> 6;               // group 0/1
    const int gtid = tid & 63;
    const int tx = gtid & 3;       // 4 i's per thread (2 f32x2 pairs)
    const int ty = gtid >> 2;      // 1 j per thread
    const int srow = gtid >> 1;    // staging row 0..31
    const bool sey_side = gtid & 1;
    unsigned long long acc0 = 0ull, acc1 = 0ull;

    for (int c = g * BKC; c < nk; c += 2 * BKC) {
        float4 v[4];
        int r = c + srow;
        if (r < nk) {
            float2 p = spt[list[r]];
            float pc = sey_side ? p.y : p.x;
            float bb = (float)(sey_side ? j0 : i0);
            #pragma unroll
            for (int q = 0; q < 4; q++) {
                float b = bb + (float)(q * 4);
                float d;
                d = pc - (b + 0.f); v[q].x = __expf(-d * d * INVC_CELL);
                d = pc - (b + 1.f); v[q].y = __expf(-d * d * INVC_CELL);
                d = pc - (b + 2.f); v[q].z = __expf(-d * d * INVC_CELL);
                d = pc - (b + 3.f); v[q].w = __expf(-d * d * INVC_CELL);
            }
        } else {
            #pragma unroll
            for (int q = 0; q < 4; q++)
                v[q] = make_float4(0.f, 0.f, 0.f, 0.f);
        }
        asm volatile("bar.sync %0, 64;" :: "r"(g + 1) : "memory");
        #pragma unroll
        for (int q = 0; q < 4; q++) {
            if (sey_side) *(float4*)&sey[g][srow][q * 4] = v[q];
            else          *(float4*)&sex[g][srow][q * 4] = v[q];
        }
        asm volatile("bar.sync %0, 64;" :: "r"(g + 1) : "memory");

        #pragma unroll
        for (int kk = 0; kk < BKC; kk++) {
            float eyv = sey[g][kk][ty];
            unsigned long long eyp;
            PACK_DUP(eyp, __float_as_uint(eyv));
            ulonglong2 exp2 = *(const ulonglong2*)&sex[g][kk][tx * 4];
            FMA_F32X2(acc0, exp2.x, eyp);
            FMA_F32X2(acc1, exp2.y, eyp);
        }
    }

    // ---- 4. fixed-order combine (g0 + g1) + write -------------------------
    if (g == 1) { gred[gtid].x = acc0; gred[gtid].y = acc1; }
    __syncthreads();
    if (g == 0) {
        unsigned a0, a1, a2, a3, b0_, b1_, b2_, b3_;
        UNPACK_F32X2(a0, a1, acc0);
        UNPACK_F32X2(a2, a3, acc1);
        ulonglong2 o = gred[gtid];
        UNPACK_F32X2(b0_, b1_, o.x);
        UNPACK_F32X2(b2_, b3_, o.y);
        float4 r;
        r.x = __uint_as_float(a0) + __uint_as_float(b0_);
        r.y = __uint_as_float(a1) + __uint_as_float(b1_);
        r.z = __uint_as_float(a2) + __uint_as_float(b2_);
        r.w = __uint_as_float(a3) + __uint_as_float(b3_);
        *(float4*)&out[(j0 + ty) * RES + i0 + tx * 4] = r;
    }
}

// ---------------------------------------------------------------------------
extern "C" void kernel_launch(void* const* d_in, const int* in_sizes, int n_in,
                              void* d_out, int out_size) {
    const float* curves = (const float*)d_in[0];
    float* out = (float*)d_out;
    k_prep<<<STRIPS, 128>>>(curves);
    dim3 grid(STRIPS, RES / TJ);
    k_tile<<<grid, 128>>>(out);
}